// round 7
// baseline (speedup 1.0000x reference)
#include <cuda_runtime.h>
#include <cstdint>
#include <math.h>

#define BB     16
#define HH     1024
#define TCNT   1500
#define MAXTOK 192
#define TS     30        // time positions per K1/K3 block (divides 1500)
#define XCOLS  32        // TS + 2 halo
#define XSTR   33        // padded smem row stride (conflict-free)
#define NTILE  50        // 1500 / TS
#define INV2T2 4.0816326530612246f   // 1/(2*0.35^2)

// ---------------- scratch (__device__ globals; no allocation) ----------------
static __device__ float g_raw[BB * TCNT];
static __device__ float g_sw[BB * TCNT];
static __device__ float g_cen[BB * TCNT];
static __device__ float g_assign[BB * TCNT * MAXTOK];   // 18.4 MB
static __device__ float g_colsum[BB * MAXTOK];
static __device__ float g_rnorm[BB * MAXTOK];
static __device__ float g_massdiff[BB];

// ---------------- packed f32x2 helpers (sm_100+ PTX) ----------------
__device__ __forceinline__ unsigned long long pk2(float a, float b) {
    unsigned long long r;
    asm("mov.b64 %0, {%1, %2};" : "=l"(r) : "f"(a), "f"(b));
    return r;
}
__device__ __forceinline__ unsigned long long fma2(unsigned long long a,
                                                   unsigned long long b,
                                                   unsigned long long c) {
    unsigned long long d;
    asm("fma.rn.f32x2 %0, %1, %2, %3;" : "=l"(d) : "l"(a), "l"(b), "l"(c));
    return d;
}
__device__ __forceinline__ unsigned long long add2(unsigned long long a,
                                                   unsigned long long b) {
    unsigned long long d;
    asm("add.rn.f32x2 %0, %1, %2;" : "=l"(d) : "l"(a), "l"(b));
    return d;
}
__device__ __forceinline__ void unpk2(unsigned long long v, float& lo, float& hi) {
    asm("mov.b64 {%0, %1}, %2;" : "=f"(lo), "=f"(hi) : "l"(v));
}

__device__ __forceinline__ int clip_tok(int t) {
    return t < 1 ? 1 : (t > MAXTOK ? MAXTOK : t);
}

// =====================================================================
// K1: fused conv1d(K=3, SAME) -> silu -> proj -> softplus -> mask  => raw[b,t]
// grid (NTILE, BB), 256 threads. Each warp owns 128 h_out as 64 pairs,
// lanes split h_in (coalesced W reads), packed f32x2 accumulators over TS.
// =====================================================================
__global__ void __launch_bounds__(256, 1)
k1_conv_raw(const float* __restrict__ enc, const float* __restrict__ cw,
            const float* __restrict__ cb, const float* __restrict__ pw,
            const float* __restrict__ pb, const int* __restrict__ elen)
{
    extern __shared__ float sh[];
    float* x_sm  = sh;                 // HH * XSTR
    float* s_raw = sh + HH * XSTR;     // TS

    const int b    = blockIdx.y;
    const int t0   = blockIdx.x * TS;
    const int tid  = threadIdx.x;
    const int lane = tid & 31;
    const int w    = tid >> 5;         // 8 warps

    if (tid < TS) s_raw[tid] = 0.f;

    const float* encb = enc + (size_t)b * HH * TCNT;
    for (int idx = tid; idx < HH * XCOLS; idx += 256) {
        int hin = idx >> 5, c = idx & 31;
        int t = t0 - 1 + c;
        float v = 0.f;
        if (t >= 0 && t < TCNT) v = encb[(size_t)hin * TCNT + t];
        x_sm[hin * XSTR + c] = v;
    }
    __syncthreads();

    float runsum = 0.f;
    #pragma unroll 1
    for (int p = 0; p < 64; ++p) {
        const int hoA = (w << 7) + (p << 1);
        const float* wAr = cw + (size_t)hoA * (HH * 3);
        const float* wBr = wAr + HH * 3;

        unsigned long long acc2[TS];
        #pragma unroll
        for (int j = 0; j < TS; ++j) acc2[j] = 0ull;

        // prefetch first weight triplets
        float a0 = wAr[lane * 3 + 0], a1 = wAr[lane * 3 + 1], a2 = wAr[lane * 3 + 2];
        float b0 = wBr[lane * 3 + 0], b1 = wBr[lane * 3 + 1], b2 = wBr[lane * 3 + 2];

        #pragma unroll 2
        for (int i = 0; i < 32; ++i) {
            unsigned long long w20 = pk2(a0, b0), w21 = pk2(a1, b1), w22 = pk2(a2, b2);
            const int hin = (i << 5) + lane;
            const float* xr = x_sm + hin * XSTR;
            if (i < 31) {   // prefetch next iteration's weights (hide L2 latency)
                int nh = ((i + 1) << 5) + lane;
                a0 = wAr[nh * 3 + 0]; a1 = wAr[nh * 3 + 1]; a2 = wAr[nh * 3 + 2];
                b0 = wBr[nh * 3 + 0]; b1 = wBr[nh * 3 + 1]; b2 = wBr[nh * 3 + 2];
            }
            #pragma unroll
            for (int c = 0; c < XCOLS; ++c) {
                float xv = xr[c];
                unsigned long long x2 = pk2(xv, xv);
                if (c < TS)            acc2[c]     = fma2(x2, w20, acc2[c]);
                if (c >= 1 && c <= TS) acc2[c - 1] = fma2(x2, w21, acc2[c - 1]);
                if (c >= 2)            acc2[c - 2] = fma2(x2, w22, acc2[c - 2]);
            }
        }

        // cross-lane reduction; lane j keeps the (hoA, hoB) sums for t = t0+j
        float mA = 0.f, mB = 0.f;
        #pragma unroll
        for (int j = 0; j < TS; ++j) {
            unsigned long long v = acc2[j];
            #pragma unroll
            for (int off = 16; off > 0; off >>= 1)
                v = add2(v, __shfl_xor_sync(0xffffffffu, v, off));
            if (lane == j) unpk2(v, mA, mB);
        }
        if (lane < TS) {
            float vA = mA + cb[hoA];
            float vB = mB + cb[hoA + 1];
            float sA = __fdividef(vA, 1.f + __expf(-vA));   // silu
            float sB = __fdividef(vB, 1.f + __expf(-vB));
            runsum += sA * pw[hoA] + sB * pw[hoA + 1];
        }
    }
    if (lane < TS) atomicAdd(&s_raw[lane], runsum);
    __syncthreads();

    if (tid < TS) {
        int t = t0 + tid;
        float x = s_raw[tid] + pb[0];
        float sp = (x > 20.f) ? x : log1pf(expf(x));   // stable softplus
        float r = sp + 1e-4f;
        if (t >= elen[b]) r = 0.f;                     // time mask
        g_raw[b * TCNT + t] = r;
    }
}

// =====================================================================
// K2: per-batch mass, scale, |mass-tok|, cumsum -> centers, sw.
// Also zeroes g_colsum. grid(BB), 512 threads.
// =====================================================================
__global__ void k2_scan(const int* __restrict__ ttl)
{
    const int b = blockIdx.x;
    const int tid = threadIdx.x;   // 512
    __shared__ float sm[16];
    __shared__ float wsum[16];
    __shared__ float sh_scale, sh_carry;

    if (tid < MAXTOK) g_colsum[b * MAXTOK + tid] = 0.f;

    float local = 0.f;
    for (int t = tid; t < TCNT; t += 512) local += g_raw[b * TCNT + t];
    #pragma unroll
    for (int off = 16; off > 0; off >>= 1)
        local += __shfl_xor_sync(0xffffffffu, local, off);
    if ((tid & 31) == 0) sm[tid >> 5] = local;
    __syncthreads();
    if (tid < 16) {
        float v = sm[tid];
        #pragma unroll
        for (int off = 8; off > 0; off >>= 1)
            v += __shfl_xor_sync(0x0000ffffu, v, off);
        if (tid == 0) {
            int tok = clip_tok(ttl[b]);
            g_massdiff[b] = fabsf(v - (float)tok);
            sh_scale = (float)tok / fmaxf(v, 1e-6f);
            sh_carry = 0.f;
        }
    }
    __syncthreads();
    const float scale = sh_scale;

    for (int tile = 0; tile < 3; ++tile) {
        int t = tile * 512 + tid;
        float v = (t < TCNT) ? g_raw[b * TCNT + t] * scale : 0.f;
        float x = v;
        #pragma unroll
        for (int off = 1; off < 32; off <<= 1) {
            float y = __shfl_up_sync(0xffffffffu, x, off);
            if ((tid & 31) >= off) x += y;
        }
        if ((tid & 31) == 31) wsum[tid >> 5] = x;
        __syncthreads();
        if (tid < 16) {
            float y = wsum[tid];
            #pragma unroll
            for (int off = 1; off < 16; off <<= 1) {
                float z = __shfl_up_sync(0x0000ffffu, y, off);
                if (tid >= off) y += z;
            }
            wsum[tid] = y;   // inclusive warp-total scan
        }
        __syncthreads();
        float offset = (tid >= 32) ? wsum[(tid >> 5) - 1] : 0.f;
        float incl = sh_carry + offset + x;
        if (t < TCNT) {
            g_cen[b * TCNT + t] = incl - 0.5f * v;
            g_sw[b * TCNT + t]  = v;
        }
        __syncthreads();
        if (tid == 0) sh_carry += wsum[15];
        __syncthreads();
    }
}

// =====================================================================
// K3: assign[b,t,k] = exp(-(center-tc_k)^2/(2*tau^2)) * sw ; + colsums
// grid (NTILE, BB), 192 threads (one per token slot).
// =====================================================================
__global__ void k3_assign()
{
    const int b  = blockIdx.y;
    const int t0 = blockIdx.x * TS;
    const int k  = threadIdx.x;   // 192
    __shared__ float sc[TS], ss[TS];
    if (k < TS) {
        sc[k] = g_cen[b * TCNT + t0 + k];
        ss[k] = g_sw[b * TCNT + t0 + k];
    }
    __syncthreads();
    const float tc = (float)k + 0.5f;
    float acc = 0.f;
    float* ap = g_assign + ((size_t)b * TCNT + t0) * MAXTOK + k;
    #pragma unroll 6
    for (int i = 0; i < TS; ++i) {
        float d = sc[i] - tc;
        float a = __expf(-d * d * INV2T2) * ss[i];
        ap[(size_t)i * MAXTOK] = a;
        acc += a;
    }
    atomicAdd(&g_colsum[b * MAXTOK + k], acc);
}

// K3b: rnorm[b,k] = tok_mask / max(colsum, eps)
__global__ void k3b_rnorm(const int* __restrict__ ttl)
{
    int b = blockIdx.x, k = threadIdx.x;
    int tok = clip_tok(ttl[b]);
    float cs = g_colsum[b * MAXTOK + k];
    g_rnorm[b * MAXTOK + k] = (k < tok) ? 1.0f / fmaxf(cs, 1e-6f) : 0.f;
}

// =====================================================================
// K4: acoustic[b,k,h] = sum_t assign[b,t,k]*rnorm[b,k] * enc[b,h,t]
// smem-tiled GEMM: BM=64(h) x BN=64(k) x BK=16(t), 256 thr, 4x4 microtile.
// grid (16, 3, 16).
// =====================================================================
__global__ void __launch_bounds__(256)
k4_gemm(const float* __restrict__ enc, float* __restrict__ out)
{
    const int b  = blockIdx.z;
    const int k0 = blockIdx.y * 64;
    const int h0 = blockIdx.x * 64;
    __shared__ float es[16][65];
    __shared__ float as[16][64];
    __shared__ float rn[64];
    const int tid = threadIdx.x;
    const int tx = tid & 15, ty = tid >> 4;
    if (tid < 64) rn[tid] = g_rnorm[b * MAXTOK + k0 + tid];

    float c[4][4];
    #pragma unroll
    for (int j = 0; j < 4; ++j)
        #pragma unroll
        for (int i = 0; i < 4; ++i) c[j][i] = 0.f;

    const float* encb = enc + ((size_t)b * HH + h0) * TCNT;
    const float* ab   = g_assign + (size_t)b * TCNT * MAXTOK + k0;

    for (int t0 = 0; t0 < TCNT; t0 += 16) {
        #pragma unroll
        for (int l = tid; l < 1024; l += 256) {
            int hh = l >> 4, tt = l & 15; int t = t0 + tt;
            es[tt][hh] = (t < TCNT) ? encb[(size_t)hh * TCNT + t] : 0.f;
        }
        #pragma unroll
        for (int l = tid; l < 1024; l += 256) {
            int tt = l >> 6, kk = l & 63; int t = t0 + tt;
            as[tt][kk] = (t < TCNT) ? ab[(size_t)t * MAXTOK + kk] : 0.f;
        }
        __syncthreads();
        #pragma unroll
        for (int tt = 0; tt < 16; ++tt) {
            float av[4], bv[4];
            #pragma unroll
            for (int i = 0; i < 4; ++i) av[i] = es[tt][ty * 4 + i];
            #pragma unroll
            for (int j = 0; j < 4; ++j) bv[j] = as[tt][tx * 4 + j];
            #pragma unroll
            for (int j = 0; j < 4; ++j)
                #pragma unroll
                for (int i = 0; i < 4; ++i) c[j][i] += bv[j] * av[i];
        }
        __syncthreads();
    }
    #pragma unroll
    for (int j = 0; j < 4; ++j) {
        float rj = rn[tx * 4 + j];
        float4 v = make_float4(c[j][0] * rj, c[j][1] * rj, c[j][2] * rj, c[j][3] * rj);
        *(float4*)(out + (((size_t)b * MAXTOK) + (k0 + tx * 4 + j)) * HH + h0 + ty * 4) = v;
    }
}

// =====================================================================
// K5: write tok_len (as float) + alignment_loss into the tail of d_out,
// zero any remaining tail padding.
// =====================================================================
__global__ void k5_final(float* __restrict__ out, const int* __restrict__ ttl, int out_size)
{
    __shared__ float s_loss;
    int tid = threadIdx.x;
    float v = (tid < BB) ? g_massdiff[tid] : 0.f;
    #pragma unroll
    for (int off = 16; off > 0; off >>= 1)
        v += __shfl_xor_sync(0xffffffffu, v, off);
    if (tid == 0) s_loss = v * (0.25f / (float)BB);
    __syncthreads();
    const int base = BB * MAXTOK * HH;   // 3145728
    for (int i = base + tid; i < out_size; i += blockDim.x) {
        int r = i - base;
        float val = 0.f;
        if (r < BB)       val = (float)clip_tok(ttl[r]);
        else if (r == BB) val = s_loss;
        out[i] = val;
    }
}

// =====================================================================
extern "C" void kernel_launch(void* const* d_in, const int* in_sizes, int n_in,
                              void* d_out, int out_size)
{
    const float* enc  = (const float*)d_in[0];
    const int*   elen = (const int*)  d_in[1];
    const int*   ttl  = (const int*)  d_in[2];
    const float* cw   = (const float*)d_in[3];
    const float* cb   = (const float*)d_in[4];
    const float* pw   = (const float*)d_in[5];
    const float* pb   = (const float*)d_in[6];
    float* out = (float*)d_out;

    const int smem1 = (HH * XSTR + TS) * (int)sizeof(float);   // ~135 KB
    cudaFuncSetAttribute(k1_conv_raw, cudaFuncAttributeMaxDynamicSharedMemorySize, smem1);

    k1_conv_raw<<<dim3(NTILE, BB), 256, smem1>>>(enc, cw, cb, pw, pb, elen);
    k2_scan<<<BB, 512>>>(ttl);
    k3_assign<<<dim3(NTILE, BB), MAXTOK>>>();
    k3b_rnorm<<<BB, MAXTOK>>>(ttl);
    k4_gemm<<<dim3(16, 3, BB), 256>>>(enc, out);
    if (out_size > BB * MAXTOK * HH)
        k5_final<<<1, 64>>>(out, ttl, out_size);
}

// round 8
// speedup vs baseline: 1.0007x; 1.0007x over previous
#include <cuda_runtime.h>
#include <cstdint>
#include <math.h>

#define BB     16
#define HH     1024
#define TCNT   1500
#define MAXTOK 192
#define TS     30        // time positions per K1/K3 block (divides 1500)
#define XCOLS  32        // TS + 2 halo
#define XSTR   33        // padded smem row stride (conflict-free)
#define NTILE  50        // 1500 / TS
#define INV2T2 4.0816326530612246f   // 1/(2*0.35^2)

// ---------------- scratch (__device__ globals; no allocation) ----------------
static __device__ float g_raw[BB * TCNT];
static __device__ float g_sw[BB * TCNT];
static __device__ float g_cen[BB * TCNT];
static __device__ float g_assign[BB * TCNT * MAXTOK];   // 18.4 MB
static __device__ float g_colsum[BB * MAXTOK];
static __device__ float g_rnorm[BB * MAXTOK];
static __device__ float g_massdiff[BB];

// ---------------- packed f32x2 helpers (sm_100+ PTX) ----------------
__device__ __forceinline__ unsigned long long pk2(float a, float b) {
    unsigned long long r;
    asm("mov.b64 %0, {%1, %2};" : "=l"(r) : "f"(a), "f"(b));
    return r;
}
__device__ __forceinline__ unsigned long long fma2(unsigned long long a,
                                                   unsigned long long b,
                                                   unsigned long long c) {
    unsigned long long d;
    asm("fma.rn.f32x2 %0, %1, %2, %3;" : "=l"(d) : "l"(a), "l"(b), "l"(c));
    return d;
}
__device__ __forceinline__ unsigned long long add2(unsigned long long a,
                                                   unsigned long long b) {
    unsigned long long d;
    asm("add.rn.f32x2 %0, %1, %2;" : "=l"(d) : "l"(a), "l"(b));
    return d;
}
__device__ __forceinline__ void unpk2(unsigned long long v, float& lo, float& hi) {
    asm("mov.b64 {%0, %1}, %2;" : "=f"(lo), "=f"(hi) : "l"(v));
}

__device__ __forceinline__ int clip_tok(int t) {
    return t < 1 ? 1 : (t > MAXTOK ? MAXTOK : t);
}

// =====================================================================
// K1: fused conv1d(K=3, SAME) -> silu -> proj -> softplus -> mask  => raw[b,t]
// grid (NTILE, BB), 256 threads. Each warp owns 128 h_out as 64 pairs,
// lanes split h_in (coalesced W reads), packed f32x2 accumulators over TS.
// =====================================================================
__global__ void __launch_bounds__(256, 1)
k1_conv_raw(const float* __restrict__ enc, const float* __restrict__ cw,
            const float* __restrict__ cb, const float* __restrict__ pw,
            const float* __restrict__ pb, const int* __restrict__ elen)
{
    extern __shared__ float sh[];
    float* x_sm  = sh;                 // HH * XSTR
    float* s_raw = sh + HH * XSTR;     // TS

    const int b    = blockIdx.y;
    const int t0   = blockIdx.x * TS;
    const int tid  = threadIdx.x;
    const int lane = tid & 31;
    const int w    = tid >> 5;         // 8 warps

    if (tid < TS) s_raw[tid] = 0.f;

    const float* encb = enc + (size_t)b * HH * TCNT;
    for (int idx = tid; idx < HH * XCOLS; idx += 256) {
        int hin = idx >> 5, c = idx & 31;
        int t = t0 - 1 + c;
        float v = 0.f;
        if (t >= 0 && t < TCNT) v = encb[(size_t)hin * TCNT + t];
        x_sm[hin * XSTR + c] = v;
    }
    __syncthreads();

    float runsum = 0.f;
    #pragma unroll 1
    for (int p = 0; p < 64; ++p) {
        const int hoA = (w << 7) + (p << 1);
        const float* wAr = cw + (size_t)hoA * (HH * 3);
        const float* wBr = wAr + HH * 3;

        unsigned long long acc2[TS];
        #pragma unroll
        for (int j = 0; j < TS; ++j) acc2[j] = 0ull;

        // prefetch first weight triplets
        float a0 = wAr[lane * 3 + 0], a1 = wAr[lane * 3 + 1], a2 = wAr[lane * 3 + 2];
        float b0 = wBr[lane * 3 + 0], b1 = wBr[lane * 3 + 1], b2 = wBr[lane * 3 + 2];

        #pragma unroll 2
        for (int i = 0; i < 32; ++i) {
            unsigned long long w20 = pk2(a0, b0), w21 = pk2(a1, b1), w22 = pk2(a2, b2);
            const int hin = (i << 5) + lane;
            const float* xr = x_sm + hin * XSTR;
            if (i < 31) {   // prefetch next iteration's weights (hide L2 latency)
                int nh = ((i + 1) << 5) + lane;
                a0 = wAr[nh * 3 + 0]; a1 = wAr[nh * 3 + 1]; a2 = wAr[nh * 3 + 2];
                b0 = wBr[nh * 3 + 0]; b1 = wBr[nh * 3 + 1]; b2 = wBr[nh * 3 + 2];
            }
            #pragma unroll
            for (int c = 0; c < XCOLS; ++c) {
                float xv = xr[c];
                unsigned long long x2 = pk2(xv, xv);
                if (c < TS)            acc2[c]     = fma2(x2, w20, acc2[c]);
                if (c >= 1 && c <= TS) acc2[c - 1] = fma2(x2, w21, acc2[c - 1]);
                if (c >= 2)            acc2[c - 2] = fma2(x2, w22, acc2[c - 2]);
            }
        }

        // cross-lane reduction; lane j keeps the (hoA, hoB) sums for t = t0+j
        float mA = 0.f, mB = 0.f;
        #pragma unroll
        for (int j = 0; j < TS; ++j) {
            unsigned long long v = acc2[j];
            #pragma unroll
            for (int off = 16; off > 0; off >>= 1)
                v = add2(v, __shfl_xor_sync(0xffffffffu, v, off));
            if (lane == j) unpk2(v, mA, mB);
        }
        if (lane < TS) {
            float vA = mA + cb[hoA];
            float vB = mB + cb[hoA + 1];
            float sA = __fdividef(vA, 1.f + __expf(-vA));   // silu
            float sB = __fdividef(vB, 1.f + __expf(-vB));
            runsum += sA * pw[hoA] + sB * pw[hoA + 1];
        }
    }
    if (lane < TS) atomicAdd(&s_raw[lane], runsum);
    __syncthreads();

    if (tid < TS) {
        int t = t0 + tid;
        float x = s_raw[tid] + pb[0];
        float sp = (x > 20.f) ? x : log1pf(expf(x));   // stable softplus
        float r = sp + 1e-4f;
        if (t >= elen[b]) r = 0.f;                     // time mask
        g_raw[b * TCNT + t] = r;
    }
}

// =====================================================================
// K2: per-batch mass, scale, |mass-tok|, cumsum -> centers, sw.
// Also zeroes g_colsum. grid(BB), 512 threads.
// =====================================================================
__global__ void k2_scan(const int* __restrict__ ttl)
{
    const int b = blockIdx.x;
    const int tid = threadIdx.x;   // 512
    __shared__ float sm[16];
    __shared__ float wsum[16];
    __shared__ float sh_scale, sh_carry;

    if (tid < MAXTOK) g_colsum[b * MAXTOK + tid] = 0.f;

    float local = 0.f;
    for (int t = tid; t < TCNT; t += 512) local += g_raw[b * TCNT + t];
    #pragma unroll
    for (int off = 16; off > 0; off >>= 1)
        local += __shfl_xor_sync(0xffffffffu, local, off);
    if ((tid & 31) == 0) sm[tid >> 5] = local;
    __syncthreads();
    if (tid < 16) {
        float v = sm[tid];
        #pragma unroll
        for (int off = 8; off > 0; off >>= 1)
            v += __shfl_xor_sync(0x0000ffffu, v, off);
        if (tid == 0) {
            int tok = clip_tok(ttl[b]);
            g_massdiff[b] = fabsf(v - (float)tok);
            sh_scale = (float)tok / fmaxf(v, 1e-6f);
            sh_carry = 0.f;
        }
    }
    __syncthreads();
    const float scale = sh_scale;

    for (int tile = 0; tile < 3; ++tile) {
        int t = tile * 512 + tid;
        float v = (t < TCNT) ? g_raw[b * TCNT + t] * scale : 0.f;
        float x = v;
        #pragma unroll
        for (int off = 1; off < 32; off <<= 1) {
            float y = __shfl_up_sync(0xffffffffu, x, off);
            if ((tid & 31) >= off) x += y;
        }
        if ((tid & 31) == 31) wsum[tid >> 5] = x;
        __syncthreads();
        if (tid < 16) {
            float y = wsum[tid];
            #pragma unroll
            for (int off = 1; off < 16; off <<= 1) {
                float z = __shfl_up_sync(0x0000ffffu, y, off);
                if (tid >= off) y += z;
            }
            wsum[tid] = y;   // inclusive warp-total scan
        }
        __syncthreads();
        float offset = (tid >= 32) ? wsum[(tid >> 5) - 1] : 0.f;
        float incl = sh_carry + offset + x;
        if (t < TCNT) {
            g_cen[b * TCNT + t] = incl - 0.5f * v;
            g_sw[b * TCNT + t]  = v;
        }
        __syncthreads();
        if (tid == 0) sh_carry += wsum[15];
        __syncthreads();
    }
}

// =====================================================================
// K3: assign[b,t,k] = exp(-(center-tc_k)^2/(2*tau^2)) * sw ; + colsums
// grid (NTILE, BB), 192 threads (one per token slot).
// =====================================================================
__global__ void k3_assign()
{
    const int b  = blockIdx.y;
    const int t0 = blockIdx.x * TS;
    const int k  = threadIdx.x;   // 192
    __shared__ float sc[TS], ss[TS];
    if (k < TS) {
        sc[k] = g_cen[b * TCNT + t0 + k];
        ss[k] = g_sw[b * TCNT + t0 + k];
    }
    __syncthreads();
    const float tc = (float)k + 0.5f;
    float acc = 0.f;
    float* ap = g_assign + ((size_t)b * TCNT + t0) * MAXTOK + k;
    #pragma unroll 6
    for (int i = 0; i < TS; ++i) {
        float d = sc[i] - tc;
        float a = __expf(-d * d * INV2T2) * ss[i];
        ap[(size_t)i * MAXTOK] = a;
        acc += a;
    }
    atomicAdd(&g_colsum[b * MAXTOK + k], acc);
}

// K3b: rnorm[b,k] = tok_mask / max(colsum, eps)
__global__ void k3b_rnorm(const int* __restrict__ ttl)
{
    int b = blockIdx.x, k = threadIdx.x;
    int tok = clip_tok(ttl[b]);
    float cs = g_colsum[b * MAXTOK + k];
    g_rnorm[b * MAXTOK + k] = (k < tok) ? 1.0f / fmaxf(cs, 1e-6f) : 0.f;
}

// =====================================================================
// K4: acoustic[b,k,h] = sum_t assign[b,t,k]*rnorm[b,k] * enc[b,h,t]
// smem-tiled GEMM: BM=64(h) x BN=64(k) x BK=16(t), 256 thr, 4x4 microtile.
// grid (16, 3, 16).
// =====================================================================
__global__ void __launch_bounds__(256)
k4_gemm(const float* __restrict__ enc, float* __restrict__ out)
{
    const int b  = blockIdx.z;
    const int k0 = blockIdx.y * 64;
    const int h0 = blockIdx.x * 64;
    __shared__ float es[16][65];
    __shared__ float as[16][64];
    __shared__ float rn[64];
    const int tid = threadIdx.x;
    const int tx = tid & 15, ty = tid >> 4;
    if (tid < 64) rn[tid] = g_rnorm[b * MAXTOK + k0 + tid];

    float c[4][4];
    #pragma unroll
    for (int j = 0; j < 4; ++j)
        #pragma unroll
        for (int i = 0; i < 4; ++i) c[j][i] = 0.f;

    const float* encb = enc + ((size_t)b * HH + h0) * TCNT;
    const float* ab   = g_assign + (size_t)b * TCNT * MAXTOK + k0;

    for (int t0 = 0; t0 < TCNT; t0 += 16) {
        #pragma unroll
        for (int l = tid; l < 1024; l += 256) {
            int hh = l >> 4, tt = l & 15; int t = t0 + tt;
            es[tt][hh] = (t < TCNT) ? encb[(size_t)hh * TCNT + t] : 0.f;
        }
        #pragma unroll
        for (int l = tid; l < 1024; l += 256) {
            int tt = l >> 6, kk = l & 63; int t = t0 + tt;
            as[tt][kk] = (t < TCNT) ? ab[(size_t)t * MAXTOK + kk] : 0.f;
        }
        __syncthreads();
        #pragma unroll
        for (int tt = 0; tt < 16; ++tt) {
            float av[4], bv[4];
            #pragma unroll
            for (int i = 0; i < 4; ++i) av[i] = es[tt][ty * 4 + i];
            #pragma unroll
            for (int j = 0; j < 4; ++j) bv[j] = as[tt][tx * 4 + j];
            #pragma unroll
            for (int j = 0; j < 4; ++j)
                #pragma unroll
                for (int i = 0; i < 4; ++i) c[j][i] += bv[j] * av[i];
        }
        __syncthreads();
    }
    #pragma unroll
    for (int j = 0; j < 4; ++j) {
        float rj = rn[tx * 4 + j];
        float4 v = make_float4(c[j][0] * rj, c[j][1] * rj, c[j][2] * rj, c[j][3] * rj);
        *(float4*)(out + (((size_t)b * MAXTOK) + (k0 + tx * 4 + j)) * HH + h0 + ty * 4) = v;
    }
}

// =====================================================================
// K5: write tok_len (as float) + alignment_loss into the tail of d_out,
// zero any remaining tail padding.
// =====================================================================
__global__ void k5_final(float* __restrict__ out, const int* __restrict__ ttl, int out_size)
{
    __shared__ float s_loss;
    int tid = threadIdx.x;
    float v = (tid < BB) ? g_massdiff[tid] : 0.f;
    #pragma unroll
    for (int off = 16; off > 0; off >>= 1)
        v += __shfl_xor_sync(0xffffffffu, v, off);
    if (tid == 0) s_loss = v * (0.25f / (float)BB);
    __syncthreads();
    const int base = BB * MAXTOK * HH;   // 3145728
    for (int i = base + tid; i < out_size; i += blockDim.x) {
        int r = i - base;
        float val = 0.f;
        if (r < BB)       val = (float)clip_tok(ttl[r]);
        else if (r == BB) val = s_loss;
        out[i] = val;
    }
}

// =====================================================================
extern "C" void kernel_launch(void* const* d_in, const int* in_sizes, int n_in,
                              void* d_out, int out_size)
{
    const float* enc  = (const float*)d_in[0];
    const int*   elen = (const int*)  d_in[1];
    const int*   ttl  = (const int*)  d_in[2];
    const float* cw   = (const float*)d_in[3];
    const float* cb   = (const float*)d_in[4];
    const float* pw   = (const float*)d_in[5];
    const float* pb   = (const float*)d_in[6];
    float* out = (float*)d_out;

    const int smem1 = (HH * XSTR + TS) * (int)sizeof(float);   // ~135 KB
    cudaFuncSetAttribute(k1_conv_raw, cudaFuncAttributeMaxDynamicSharedMemorySize, smem1);

    k1_conv_raw<<<dim3(NTILE, BB), 256, smem1>>>(enc, cw, cb, pw, pb, elen);
    k2_scan<<<BB, 512>>>(ttl);
    k3_assign<<<dim3(NTILE, BB), MAXTOK>>>();
    k3b_rnorm<<<BB, MAXTOK>>>(ttl);
    k4_gemm<<<dim3(16, 3, BB), 256>>>(enc, out);
    if (out_size > BB * MAXTOK * HH)
        k5_final<<<1, 64>>>(out, ttl, out_size);
}

// round 9
// speedup vs baseline: 1.0010x; 1.0003x over previous
#include <cuda_runtime.h>
#include <cstdint>
#include <math.h>

#define BB     16
#define HH     1024
#define TCNT   1500
#define MAXTOK 192
#define TS     30        // time positions per K1/K3 block (divides 1500)
#define XCOLS  32        // TS + 2 halo
#define XSTR   33        // padded smem row stride (conflict-free)
#define NTILE  50        // 1500 / TS
#define INV2T2 4.0816326530612246f   // 1/(2*0.35^2)

// ---------------- scratch (__device__ globals; no allocation) ----------------
static __device__ float g_raw[BB * TCNT];
static __device__ float g_sw[BB * TCNT];
static __device__ float g_cen[BB * TCNT];
static __device__ float g_assign[BB * TCNT * MAXTOK];   // 18.4 MB
static __device__ float g_colsum[BB * MAXTOK];
static __device__ float g_rnorm[BB * MAXTOK];
static __device__ float g_massdiff[BB];

// ---------------- packed f32x2 helpers (sm_100+ PTX) ----------------
__device__ __forceinline__ unsigned long long pk2(float a, float b) {
    unsigned long long r;
    asm("mov.b64 %0, {%1, %2};" : "=l"(r) : "f"(a), "f"(b));
    return r;
}
__device__ __forceinline__ unsigned long long fma2(unsigned long long a,
                                                   unsigned long long b,
                                                   unsigned long long c) {
    unsigned long long d;
    asm("fma.rn.f32x2 %0, %1, %2, %3;" : "=l"(d) : "l"(a), "l"(b), "l"(c));
    return d;
}
__device__ __forceinline__ unsigned long long add2(unsigned long long a,
                                                   unsigned long long b) {
    unsigned long long d;
    asm("add.rn.f32x2 %0, %1, %2;" : "=l"(d) : "l"(a), "l"(b));
    return d;
}
__device__ __forceinline__ void unpk2(unsigned long long v, float& lo, float& hi) {
    asm("mov.b64 {%0, %1}, %2;" : "=f"(lo), "=f"(hi) : "l"(v));
}

__device__ __forceinline__ int clip_tok(int t) {
    return t < 1 ? 1 : (t > MAXTOK ? MAXTOK : t);
}

// =====================================================================
// K1: fused conv1d(K=3, SAME) -> silu -> proj -> softplus -> mask  => raw[b,t]
// grid (NTILE, BB), 256 threads. Each warp owns 128 h_out as 64 pairs,
// lanes split h_in (coalesced W reads), packed f32x2 accumulators over TS.
// =====================================================================
__global__ void __launch_bounds__(256, 1)
k1_conv_raw(const float* __restrict__ enc, const float* __restrict__ cw,
            const float* __restrict__ cb, const float* __restrict__ pw,
            const float* __restrict__ pb, const int* __restrict__ elen)
{
    extern __shared__ float sh[];
    float* x_sm  = sh;                 // HH * XSTR
    float* s_raw = sh + HH * XSTR;     // TS

    const int b    = blockIdx.y;
    const int t0   = blockIdx.x * TS;
    const int tid  = threadIdx.x;
    const int lane = tid & 31;
    const int w    = tid >> 5;         // 8 warps

    if (tid < TS) s_raw[tid] = 0.f;

    const float* encb = enc + (size_t)b * HH * TCNT;
    for (int idx = tid; idx < HH * XCOLS; idx += 256) {
        int hin = idx >> 5, c = idx & 31;
        int t = t0 - 1 + c;
        float v = 0.f;
        if (t >= 0 && t < TCNT) v = encb[(size_t)hin * TCNT + t];
        x_sm[hin * XSTR + c] = v;
    }
    __syncthreads();

    float runsum = 0.f;
    #pragma unroll 1
    for (int p = 0; p < 64; ++p) {
        const int hoA = (w << 7) + (p << 1);
        const float* wAr = cw + (size_t)hoA * (HH * 3);
        const float* wBr = wAr + HH * 3;

        unsigned long long acc2[TS];
        #pragma unroll
        for (int j = 0; j < TS; ++j) acc2[j] = 0ull;

        // prefetch first weight triplets
        float a0 = wAr[lane * 3 + 0], a1 = wAr[lane * 3 + 1], a2 = wAr[lane * 3 + 2];
        float b0 = wBr[lane * 3 + 0], b1 = wBr[lane * 3 + 1], b2 = wBr[lane * 3 + 2];

        #pragma unroll 2
        for (int i = 0; i < 32; ++i) {
            unsigned long long w20 = pk2(a0, b0), w21 = pk2(a1, b1), w22 = pk2(a2, b2);
            const int hin = (i << 5) + lane;
            const float* xr = x_sm + hin * XSTR;
            if (i < 31) {   // prefetch next iteration's weights (hide L2 latency)
                int nh = ((i + 1) << 5) + lane;
                a0 = wAr[nh * 3 + 0]; a1 = wAr[nh * 3 + 1]; a2 = wAr[nh * 3 + 2];
                b0 = wBr[nh * 3 + 0]; b1 = wBr[nh * 3 + 1]; b2 = wBr[nh * 3 + 2];
            }
            #pragma unroll
            for (int c = 0; c < XCOLS; ++c) {
                float xv = xr[c];
                unsigned long long x2 = pk2(xv, xv);
                if (c < TS)            acc2[c]     = fma2(x2, w20, acc2[c]);
                if (c >= 1 && c <= TS) acc2[c - 1] = fma2(x2, w21, acc2[c - 1]);
                if (c >= 2)            acc2[c - 2] = fma2(x2, w22, acc2[c - 2]);
            }
        }

        // cross-lane reduction; lane j keeps the (hoA, hoB) sums for t = t0+j
        float mA = 0.f, mB = 0.f;
        #pragma unroll
        for (int j = 0; j < TS; ++j) {
            unsigned long long v = acc2[j];
            #pragma unroll
            for (int off = 16; off > 0; off >>= 1)
                v = add2(v, __shfl_xor_sync(0xffffffffu, v, off));
            if (lane == j) unpk2(v, mA, mB);
        }
        if (lane < TS) {
            float vA = mA + cb[hoA];
            float vB = mB + cb[hoA + 1];
            float sA = __fdividef(vA, 1.f + __expf(-vA));   // silu
            float sB = __fdividef(vB, 1.f + __expf(-vB));
            runsum += sA * pw[hoA] + sB * pw[hoA + 1];
        }
    }
    if (lane < TS) atomicAdd(&s_raw[lane], runsum);
    __syncthreads();

    if (tid < TS) {
        int t = t0 + tid;
        float x = s_raw[tid] + pb[0];
        float sp = (x > 20.f) ? x : log1pf(expf(x));   // stable softplus
        float r = sp + 1e-4f;
        if (t >= elen[b]) r = 0.f;                     // time mask
        g_raw[b * TCNT + t] = r;
    }
}

// =====================================================================
// K2: per-batch mass, scale, |mass-tok|, cumsum -> centers, sw.
// Also zeroes g_colsum. grid(BB), 512 threads.
// =====================================================================
__global__ void k2_scan(const int* __restrict__ ttl)
{
    const int b = blockIdx.x;
    const int tid = threadIdx.x;   // 512
    __shared__ float sm[16];
    __shared__ float wsum[16];
    __shared__ float sh_scale, sh_carry;

    if (tid < MAXTOK) g_colsum[b * MAXTOK + tid] = 0.f;

    float local = 0.f;
    for (int t = tid; t < TCNT; t += 512) local += g_raw[b * TCNT + t];
    #pragma unroll
    for (int off = 16; off > 0; off >>= 1)
        local += __shfl_xor_sync(0xffffffffu, local, off);
    if ((tid & 31) == 0) sm[tid >> 5] = local;
    __syncthreads();
    if (tid < 16) {
        float v = sm[tid];
        #pragma unroll
        for (int off = 8; off > 0; off >>= 1)
            v += __shfl_xor_sync(0x0000ffffu, v, off);
        if (tid == 0) {
            int tok = clip_tok(ttl[b]);
            g_massdiff[b] = fabsf(v - (float)tok);
            sh_scale = (float)tok / fmaxf(v, 1e-6f);
            sh_carry = 0.f;
        }
    }
    __syncthreads();
    const float scale = sh_scale;

    for (int tile = 0; tile < 3; ++tile) {
        int t = tile * 512 + tid;
        float v = (t < TCNT) ? g_raw[b * TCNT + t] * scale : 0.f;
        float x = v;
        #pragma unroll
        for (int off = 1; off < 32; off <<= 1) {
            float y = __shfl_up_sync(0xffffffffu, x, off);
            if ((tid & 31) >= off) x += y;
        }
        if ((tid & 31) == 31) wsum[tid >> 5] = x;
        __syncthreads();
        if (tid < 16) {
            float y = wsum[tid];
            #pragma unroll
            for (int off = 1; off < 16; off <<= 1) {
                float z = __shfl_up_sync(0x0000ffffu, y, off);
                if (tid >= off) y += z;
            }
            wsum[tid] = y;   // inclusive warp-total scan
        }
        __syncthreads();
        float offset = (tid >= 32) ? wsum[(tid >> 5) - 1] : 0.f;
        float incl = sh_carry + offset + x;
        if (t < TCNT) {
            g_cen[b * TCNT + t] = incl - 0.5f * v;
            g_sw[b * TCNT + t]  = v;
        }
        __syncthreads();
        if (tid == 0) sh_carry += wsum[15];
        __syncthreads();
    }
}

// =====================================================================
// K3: assign[b,t,k] = exp(-(center-tc_k)^2/(2*tau^2)) * sw ; + colsums
// grid (NTILE, BB), 192 threads (one per token slot).
// =====================================================================
__global__ void k3_assign()
{
    const int b  = blockIdx.y;
    const int t0 = blockIdx.x * TS;
    const int k  = threadIdx.x;   // 192
    __shared__ float sc[TS], ss[TS];
    if (k < TS) {
        sc[k] = g_cen[b * TCNT + t0 + k];
        ss[k] = g_sw[b * TCNT + t0 + k];
    }
    __syncthreads();
    const float tc = (float)k + 0.5f;
    float acc = 0.f;
    float* ap = g_assign + ((size_t)b * TCNT + t0) * MAXTOK + k;
    #pragma unroll 6
    for (int i = 0; i < TS; ++i) {
        float d = sc[i] - tc;
        float a = __expf(-d * d * INV2T2) * ss[i];
        ap[(size_t)i * MAXTOK] = a;
        acc += a;
    }
    atomicAdd(&g_colsum[b * MAXTOK + k], acc);
}

// K3b: rnorm[b,k] = tok_mask / max(colsum, eps)
__global__ void k3b_rnorm(const int* __restrict__ ttl)
{
    int b = blockIdx.x, k = threadIdx.x;
    int tok = clip_tok(ttl[b]);
    float cs = g_colsum[b * MAXTOK + k];
    g_rnorm[b * MAXTOK + k] = (k < tok) ? 1.0f / fmaxf(cs, 1e-6f) : 0.f;
}

// =====================================================================
// K4: acoustic[b,k,h] = sum_t assign[b,t,k]*rnorm[b,k] * enc[b,h,t]
// smem-tiled GEMM: BM=64(h) x BN=64(k) x BK=16(t), 256 thr, 4x4 microtile.
// grid (16, 3, 16).
// =====================================================================
__global__ void __launch_bounds__(256)
k4_gemm(const float* __restrict__ enc, float* __restrict__ out)
{
    const int b  = blockIdx.z;
    const int k0 = blockIdx.y * 64;
    const int h0 = blockIdx.x * 64;
    __shared__ float es[16][65];
    __shared__ float as[16][64];
    __shared__ float rn[64];
    const int tid = threadIdx.x;
    const int tx = tid & 15, ty = tid >> 4;
    if (tid < 64) rn[tid] = g_rnorm[b * MAXTOK + k0 + tid];

    float c[4][4];
    #pragma unroll
    for (int j = 0; j < 4; ++j)
        #pragma unroll
        for (int i = 0; i < 4; ++i) c[j][i] = 0.f;

    const float* encb = enc + ((size_t)b * HH + h0) * TCNT;
    const float* ab   = g_assign + (size_t)b * TCNT * MAXTOK + k0;

    for (int t0 = 0; t0 < TCNT; t0 += 16) {
        #pragma unroll
        for (int l = tid; l < 1024; l += 256) {
            int hh = l >> 4, tt = l & 15; int t = t0 + tt;
            es[tt][hh] = (t < TCNT) ? encb[(size_t)hh * TCNT + t] : 0.f;
        }
        #pragma unroll
        for (int l = tid; l < 1024; l += 256) {
            int tt = l >> 6, kk = l & 63; int t = t0 + tt;
            as[tt][kk] = (t < TCNT) ? ab[(size_t)t * MAXTOK + kk] : 0.f;
        }
        __syncthreads();
        #pragma unroll
        for (int tt = 0; tt < 16; ++tt) {
            float av[4], bv[4];
            #pragma unroll
            for (int i = 0; i < 4; ++i) av[i] = es[tt][ty * 4 + i];
            #pragma unroll
            for (int j = 0; j < 4; ++j) bv[j] = as[tt][tx * 4 + j];
            #pragma unroll
            for (int j = 0; j < 4; ++j)
                #pragma unroll
                for (int i = 0; i < 4; ++i) c[j][i] += bv[j] * av[i];
        }
        __syncthreads();
    }
    #pragma unroll
    for (int j = 0; j < 4; ++j) {
        float rj = rn[tx * 4 + j];
        float4 v = make_float4(c[j][0] * rj, c[j][1] * rj, c[j][2] * rj, c[j][3] * rj);
        *(float4*)(out + (((size_t)b * MAXTOK) + (k0 + tx * 4 + j)) * HH + h0 + ty * 4) = v;
    }
}

// =====================================================================
// K5: write tok_len (as float) + alignment_loss into the tail of d_out,
// zero any remaining tail padding.
// =====================================================================
__global__ void k5_final(float* __restrict__ out, const int* __restrict__ ttl, int out_size)
{
    __shared__ float s_loss;
    int tid = threadIdx.x;
    float v = (tid < BB) ? g_massdiff[tid] : 0.f;
    #pragma unroll
    for (int off = 16; off > 0; off >>= 1)
        v += __shfl_xor_sync(0xffffffffu, v, off);
    if (tid == 0) s_loss = v * (0.25f / (float)BB);
    __syncthreads();
    const int base = BB * MAXTOK * HH;   // 3145728
    for (int i = base + tid; i < out_size; i += blockDim.x) {
        int r = i - base;
        float val = 0.f;
        if (r < BB)       val = (float)clip_tok(ttl[r]);
        else if (r == BB) val = s_loss;
        out[i] = val;
    }
}

// =====================================================================
extern "C" void kernel_launch(void* const* d_in, const int* in_sizes, int n_in,
                              void* d_out, int out_size)
{
    const float* enc  = (const float*)d_in[0];
    const int*   elen = (const int*)  d_in[1];
    const int*   ttl  = (const int*)  d_in[2];
    const float* cw   = (const float*)d_in[3];
    const float* cb   = (const float*)d_in[4];
    const float* pw   = (const float*)d_in[5];
    const float* pb   = (const float*)d_in[6];
    float* out = (float*)d_out;

    const int smem1 = (HH * XSTR + TS) * (int)sizeof(float);   // ~135 KB
    cudaFuncSetAttribute(k1_conv_raw, cudaFuncAttributeMaxDynamicSharedMemorySize, smem1);

    k1_conv_raw<<<dim3(NTILE, BB), 256, smem1>>>(enc, cw, cb, pw, pb, elen);
    k2_scan<<<BB, 512>>>(ttl);
    k3_assign<<<dim3(NTILE, BB), MAXTOK>>>();
    k3b_rnorm<<<BB, MAXTOK>>>(ttl);
    k4_gemm<<<dim3(16, 3, BB), 256>>>(enc, out);
    if (out_size > BB * MAXTOK * HH)
        k5_final<<<1, 64>>>(out, ttl, out_size);
}

// round 10
// speedup vs baseline: 1.0016x; 1.0007x over previous
#include <cuda_runtime.h>
#include <cstdint>
#include <math.h>

#define BB     16
#define HH     1024
#define TCNT   1500
#define MAXTOK 192
#define TS     30        // time positions per K1/K3 block (divides 1500)
#define XCOLS  32        // TS + 2 halo
#define XSTR   33        // padded smem row stride (conflict-free)
#define NTILE  50        // 1500 / TS
#define INV2T2 4.0816326530612246f   // 1/(2*0.35^2)

// ---------------- scratch (__device__ globals; no allocation) ----------------
static __device__ float g_raw[BB * TCNT];
static __device__ float g_sw[BB * TCNT];
static __device__ float g_cen[BB * TCNT];
static __device__ float g_assign[BB * TCNT * MAXTOK];   // 18.4 MB
static __device__ float g_colsum[BB * MAXTOK];
static __device__ float g_rnorm[BB * MAXTOK];
static __device__ float g_massdiff[BB];

// ---------------- packed f32x2 helpers (sm_100+ PTX) ----------------
__device__ __forceinline__ unsigned long long pk2(float a, float b) {
    unsigned long long r;
    asm("mov.b64 %0, {%1, %2};" : "=l"(r) : "f"(a), "f"(b));
    return r;
}
__device__ __forceinline__ unsigned long long fma2(unsigned long long a,
                                                   unsigned long long b,
                                                   unsigned long long c) {
    unsigned long long d;
    asm("fma.rn.f32x2 %0, %1, %2, %3;" : "=l"(d) : "l"(a), "l"(b), "l"(c));
    return d;
}
__device__ __forceinline__ unsigned long long add2(unsigned long long a,
                                                   unsigned long long b) {
    unsigned long long d;
    asm("add.rn.f32x2 %0, %1, %2;" : "=l"(d) : "l"(a), "l"(b));
    return d;
}
__device__ __forceinline__ void unpk2(unsigned long long v, float& lo, float& hi) {
    asm("mov.b64 {%0, %1}, %2;" : "=f"(lo), "=f"(hi) : "l"(v));
}

__device__ __forceinline__ int clip_tok(int t) {
    return t < 1 ? 1 : (t > MAXTOK ? MAXTOK : t);
}

// =====================================================================
// K1: fused conv1d(K=3, SAME) -> silu -> proj -> softplus -> mask  => raw[b,t]
// grid (NTILE, BB), 256 threads. Each warp owns 128 h_out as 64 pairs,
// lanes split h_in (coalesced W reads), packed f32x2 accumulators over TS.
// =====================================================================
__global__ void __launch_bounds__(256, 1)
k1_conv_raw(const float* __restrict__ enc, const float* __restrict__ cw,
            const float* __restrict__ cb, const float* __restrict__ pw,
            const float* __restrict__ pb, const int* __restrict__ elen)
{
    extern __shared__ float sh[];
    float* x_sm  = sh;                 // HH * XSTR
    float* s_raw = sh + HH * XSTR;     // TS

    const int b    = blockIdx.y;
    const int t0   = blockIdx.x * TS;
    const int tid  = threadIdx.x;
    const int lane = tid & 31;
    const int w    = tid >> 5;         // 8 warps

    if (tid < TS) s_raw[tid] = 0.f;

    const float* encb = enc + (size_t)b * HH * TCNT;
    for (int idx = tid; idx < HH * XCOLS; idx += 256) {
        int hin = idx >> 5, c = idx & 31;
        int t = t0 - 1 + c;
        float v = 0.f;
        if (t >= 0 && t < TCNT) v = encb[(size_t)hin * TCNT + t];
        x_sm[hin * XSTR + c] = v;
    }
    __syncthreads();

    float runsum = 0.f;
    #pragma unroll 1
    for (int p = 0; p < 64; ++p) {
        const int hoA = (w << 7) + (p << 1);
        const float* wAr = cw + (size_t)hoA * (HH * 3);
        const float* wBr = wAr + HH * 3;

        unsigned long long acc2[TS];
        #pragma unroll
        for (int j = 0; j < TS; ++j) acc2[j] = 0ull;

        // prefetch first weight triplets
        float a0 = wAr[lane * 3 + 0], a1 = wAr[lane * 3 + 1], a2 = wAr[lane * 3 + 2];
        float b0 = wBr[lane * 3 + 0], b1 = wBr[lane * 3 + 1], b2 = wBr[lane * 3 + 2];

        #pragma unroll 2
        for (int i = 0; i < 32; ++i) {
            unsigned long long w20 = pk2(a0, b0), w21 = pk2(a1, b1), w22 = pk2(a2, b2);
            const int hin = (i << 5) + lane;
            const float* xr = x_sm + hin * XSTR;
            if (i < 31) {   // prefetch next iteration's weights (hide L2 latency)
                int nh = ((i + 1) << 5) + lane;
                a0 = wAr[nh * 3 + 0]; a1 = wAr[nh * 3 + 1]; a2 = wAr[nh * 3 + 2];
                b0 = wBr[nh * 3 + 0]; b1 = wBr[nh * 3 + 1]; b2 = wBr[nh * 3 + 2];
            }
            #pragma unroll
            for (int c = 0; c < XCOLS; ++c) {
                float xv = xr[c];
                unsigned long long x2 = pk2(xv, xv);
                if (c < TS)            acc2[c]     = fma2(x2, w20, acc2[c]);
                if (c >= 1 && c <= TS) acc2[c - 1] = fma2(x2, w21, acc2[c - 1]);
                if (c >= 2)            acc2[c - 2] = fma2(x2, w22, acc2[c - 2]);
            }
        }

        // cross-lane reduction; lane j keeps the (hoA, hoB) sums for t = t0+j
        float mA = 0.f, mB = 0.f;
        #pragma unroll
        for (int j = 0; j < TS; ++j) {
            unsigned long long v = acc2[j];
            #pragma unroll
            for (int off = 16; off > 0; off >>= 1)
                v = add2(v, __shfl_xor_sync(0xffffffffu, v, off));
            if (lane == j) unpk2(v, mA, mB);
        }
        if (lane < TS) {
            float vA = mA + cb[hoA];
            float vB = mB + cb[hoA + 1];
            float sA = __fdividef(vA, 1.f + __expf(-vA));   // silu
            float sB = __fdividef(vB, 1.f + __expf(-vB));
            runsum += sA * pw[hoA] + sB * pw[hoA + 1];
        }
    }
    if (lane < TS) atomicAdd(&s_raw[lane], runsum);
    __syncthreads();

    if (tid < TS) {
        int t = t0 + tid;
        float x = s_raw[tid] + pb[0];
        float sp = (x > 20.f) ? x : log1pf(expf(x));   // stable softplus
        float r = sp + 1e-4f;
        if (t >= elen[b]) r = 0.f;                     // time mask
        g_raw[b * TCNT + t] = r;
    }
}

// =====================================================================
// K2: per-batch mass, scale, |mass-tok|, cumsum -> centers, sw.
// Also zeroes g_colsum. grid(BB), 512 threads.
// =====================================================================
__global__ void k2_scan(const int* __restrict__ ttl)
{
    const int b = blockIdx.x;
    const int tid = threadIdx.x;   // 512
    __shared__ float sm[16];
    __shared__ float wsum[16];
    __shared__ float sh_scale, sh_carry;

    if (tid < MAXTOK) g_colsum[b * MAXTOK + tid] = 0.f;

    float local = 0.f;
    for (int t = tid; t < TCNT; t += 512) local += g_raw[b * TCNT + t];
    #pragma unroll
    for (int off = 16; off > 0; off >>= 1)
        local += __shfl_xor_sync(0xffffffffu, local, off);
    if ((tid & 31) == 0) sm[tid >> 5] = local;
    __syncthreads();
    if (tid < 16) {
        float v = sm[tid];
        #pragma unroll
        for (int off = 8; off > 0; off >>= 1)
            v += __shfl_xor_sync(0x0000ffffu, v, off);
        if (tid == 0) {
            int tok = clip_tok(ttl[b]);
            g_massdiff[b] = fabsf(v - (float)tok);
            sh_scale = (float)tok / fmaxf(v, 1e-6f);
            sh_carry = 0.f;
        }
    }
    __syncthreads();
    const float scale = sh_scale;

    for (int tile = 0; tile < 3; ++tile) {
        int t = tile * 512 + tid;
        float v = (t < TCNT) ? g_raw[b * TCNT + t] * scale : 0.f;
        float x = v;
        #pragma unroll
        for (int off = 1; off < 32; off <<= 1) {
            float y = __shfl_up_sync(0xffffffffu, x, off);
            if ((tid & 31) >= off) x += y;
        }
        if ((tid & 31) == 31) wsum[tid >> 5] = x;
        __syncthreads();
        if (tid < 16) {
            float y = wsum[tid];
            #pragma unroll
            for (int off = 1; off < 16; off <<= 1) {
                float z = __shfl_up_sync(0x0000ffffu, y, off);
                if (tid >= off) y += z;
            }
            wsum[tid] = y;   // inclusive warp-total scan
        }
        __syncthreads();
        float offset = (tid >= 32) ? wsum[(tid >> 5) - 1] : 0.f;
        float incl = sh_carry + offset + x;
        if (t < TCNT) {
            g_cen[b * TCNT + t] = incl - 0.5f * v;
            g_sw[b * TCNT + t]  = v;
        }
        __syncthreads();
        if (tid == 0) sh_carry += wsum[15];
        __syncthreads();
    }
}

// =====================================================================
// K3: assign[b,t,k] = exp(-(center-tc_k)^2/(2*tau^2)) * sw ; + colsums
// grid (NTILE, BB), 192 threads (one per token slot).
// =====================================================================
__global__ void k3_assign()
{
    const int b  = blockIdx.y;
    const int t0 = blockIdx.x * TS;
    const int k  = threadIdx.x;   // 192
    __shared__ float sc[TS], ss[TS];
    if (k < TS) {
        sc[k] = g_cen[b * TCNT + t0 + k];
        ss[k] = g_sw[b * TCNT + t0 + k];
    }
    __syncthreads();
    const float tc = (float)k + 0.5f;
    float acc = 0.f;
    float* ap = g_assign + ((size_t)b * TCNT + t0) * MAXTOK + k;
    #pragma unroll 6
    for (int i = 0; i < TS; ++i) {
        float d = sc[i] - tc;
        float a = __expf(-d * d * INV2T2) * ss[i];
        ap[(size_t)i * MAXTOK] = a;
        acc += a;
    }
    atomicAdd(&g_colsum[b * MAXTOK + k], acc);
}

// K3b: rnorm[b,k] = tok_mask / max(colsum, eps)
__global__ void k3b_rnorm(const int* __restrict__ ttl)
{
    int b = blockIdx.x, k = threadIdx.x;
    int tok = clip_tok(ttl[b]);
    float cs = g_colsum[b * MAXTOK + k];
    g_rnorm[b * MAXTOK + k] = (k < tok) ? 1.0f / fmaxf(cs, 1e-6f) : 0.f;
}

// =====================================================================
// K4: acoustic[b,k,h] = sum_t assign[b,t,k]*rnorm[b,k] * enc[b,h,t]
// smem-tiled GEMM: BM=64(h) x BN=64(k) x BK=16(t), 256 thr, 4x4 microtile.
// grid (16, 3, 16).
// =====================================================================
__global__ void __launch_bounds__(256)
k4_gemm(const float* __restrict__ enc, float* __restrict__ out)
{
    const int b  = blockIdx.z;
    const int k0 = blockIdx.y * 64;
    const int h0 = blockIdx.x * 64;
    __shared__ float es[16][65];
    __shared__ float as[16][64];
    __shared__ float rn[64];
    const int tid = threadIdx.x;
    const int tx = tid & 15, ty = tid >> 4;
    if (tid < 64) rn[tid] = g_rnorm[b * MAXTOK + k0 + tid];

    float c[4][4];
    #pragma unroll
    for (int j = 0; j < 4; ++j)
        #pragma unroll
        for (int i = 0; i < 4; ++i) c[j][i] = 0.f;

    const float* encb = enc + ((size_t)b * HH + h0) * TCNT;
    const float* ab   = g_assign + (size_t)b * TCNT * MAXTOK + k0;

    for (int t0 = 0; t0 < TCNT; t0 += 16) {
        #pragma unroll
        for (int l = tid; l < 1024; l += 256) {
            int hh = l >> 4, tt = l & 15; int t = t0 + tt;
            es[tt][hh] = (t < TCNT) ? encb[(size_t)hh * TCNT + t] : 0.f;
        }
        #pragma unroll
        for (int l = tid; l < 1024; l += 256) {
            int tt = l >> 6, kk = l & 63; int t = t0 + tt;
            as[tt][kk] = (t < TCNT) ? ab[(size_t)t * MAXTOK + kk] : 0.f;
        }
        __syncthreads();
        #pragma unroll
        for (int tt = 0; tt < 16; ++tt) {
            float av[4], bv[4];
            #pragma unroll
            for (int i = 0; i < 4; ++i) av[i] = es[tt][ty * 4 + i];
            #pragma unroll
            for (int j = 0; j < 4; ++j) bv[j] = as[tt][tx * 4 + j];
            #pragma unroll
            for (int j = 0; j < 4; ++j)
                #pragma unroll
                for (int i = 0; i < 4; ++i) c[j][i] += bv[j] * av[i];
        }
        __syncthreads();
    }
    #pragma unroll
    for (int j = 0; j < 4; ++j) {
        float rj = rn[tx * 4 + j];
        float4 v = make_float4(c[j][0] * rj, c[j][1] * rj, c[j][2] * rj, c[j][3] * rj);
        *(float4*)(out + (((size_t)b * MAXTOK) + (k0 + tx * 4 + j)) * HH + h0 + ty * 4) = v;
    }
}

// =====================================================================
// K5: write tok_len (as float) + alignment_loss into the tail of d_out,
// zero any remaining tail padding.
// =====================================================================
__global__ void k5_final(float* __restrict__ out, const int* __restrict__ ttl, int out_size)
{
    __shared__ float s_loss;
    int tid = threadIdx.x;
    float v = (tid < BB) ? g_massdiff[tid] : 0.f;
    #pragma unroll
    for (int off = 16; off > 0; off >>= 1)
        v += __shfl_xor_sync(0xffffffffu, v, off);
    if (tid == 0) s_loss = v * (0.25f / (float)BB);
    __syncthreads();
    const int base = BB * MAXTOK * HH;   // 3145728
    for (int i = base + tid; i < out_size; i += blockDim.x) {
        int r = i - base;
        float val = 0.f;
        if (r < BB)       val = (float)clip_tok(ttl[r]);
        else if (r == BB) val = s_loss;
        out[i] = val;
    }
}

// =====================================================================
extern "C" void kernel_launch(void* const* d_in, const int* in_sizes, int n_in,
                              void* d_out, int out_size)
{
    const float* enc  = (const float*)d_in[0];
    const int*   elen = (const int*)  d_in[1];
    const int*   ttl  = (const int*)  d_in[2];
    const float* cw   = (const float*)d_in[3];
    const float* cb   = (const float*)d_in[4];
    const float* pw   = (const float*)d_in[5];
    const float* pb   = (const float*)d_in[6];
    float* out = (float*)d_out;

    const int smem1 = (HH * XSTR + TS) * (int)sizeof(float);   // ~135 KB
    cudaFuncSetAttribute(k1_conv_raw, cudaFuncAttributeMaxDynamicSharedMemorySize, smem1);

    k1_conv_raw<<<dim3(NTILE, BB), 256, smem1>>>(enc, cw, cb, pw, pb, elen);
    k2_scan<<<BB, 512>>>(ttl);
    k3_assign<<<dim3(NTILE, BB), MAXTOK>>>();
    k3b_rnorm<<<BB, MAXTOK>>>(ttl);
    k4_gemm<<<dim3(16, 3, BB), 256>>>(enc, out);
    if (out_size > BB * MAXTOK * HH)
        k5_final<<<1, 64>>>(out, ttl, out_size);
}